// round 12
// baseline (speedup 1.0000x reference)
#include <cuda_runtime.h>
#include <cuda_fp16.h>
#include <math.h>
#include <stdint.h>

#define T_ 4096
#define D_ 512
#define TR_ 64
#define CC_ 64
#define L_ 3
#define F_ 8192
#define NCH_ 4096
#define NCHUNK_ 64
#define CHUNK_ 64
#define NSPLIT0_ 9
#define NSPLIT1_ 2

// ---------------- scratch ----------------
__device__ float g_x[T_*D_];
__device__ float g_u[T_*TR_];
__device__ float g_v[T_*CC_];
__device__ float2 g_Bend[NCHUNK_*NCH_];
__device__ float2 g_Amat[NCHUNK_*NCH_];
__device__ float2 g_dec[L_*NCH_];
__device__ float2 g_decL[L_*NCH_];
__device__ float g_hp[NSPLIT0_][T_*D_];
__device__ float g_ztmp[T_*D_];
__device__ __half g_sclh[(size_t)T_*F_];
__device__ __half g_w0h[L_*D_*F_];
__device__ __half g_w1h[L_*D_*D_];
__device__ __half g_wph[L_*128*D_];
__device__ __half g_z0h[T_*D_];
__device__ __half g_xh[T_*D_];

// ---------------- low-level helpers (baseline PTX @ compute_103) ----------------
__device__ __forceinline__ uint32_t sptr(const void* p){
  return (uint32_t)__cvta_generic_to_shared(p);
}
__device__ __forceinline__ void cp16(uint32_t s, const void* g){
  asm volatile("cp.async.cg.shared.global [%0], [%1], 16;" :: "r"(s), "l"(g));
}
#define CP_COMMIT() asm volatile("cp.async.commit_group;" ::: "memory")
#define CP_WAIT(n)  asm volatile("cp.async.wait_group %0;" :: "n"(n) : "memory")

__device__ __forceinline__ void ldsm4(uint32_t* r, uint32_t a){
  asm volatile("ldmatrix.sync.aligned.m8n8.x4.shared.b16 {%0,%1,%2,%3}, [%4];"
    : "=r"(r[0]),"=r"(r[1]),"=r"(r[2]),"=r"(r[3]) : "r"(a));
}
__device__ __forceinline__ void mma_h(float* d, const uint32_t* a, const uint32_t* b){
  asm volatile("mma.sync.aligned.m16n8k16.row.col.f32.f16.f16.f32 "
    "{%0,%1,%2,%3}, {%4,%5,%6,%7}, {%8,%9}, {%0,%1,%2,%3};"
    : "+f"(d[0]),"+f"(d[1]),"+f"(d[2]),"+f"(d[3])
    : "r"(a[0]),"r"(a[1]),"r"(a[2]),"r"(a[3]), "r"(b[0]),"r"(b[1]));
}

// ---------------- merged prep kernel ----------------
#define NW0 (L_*D_*F_)
#define NW1 (L_*D_*D_)
#define NWP (L_*128*D_)
#define NX  (T_*D_)
#define NDEC (L_*NCH_)
#define NPREP (NW0+NW1+NWP+NX+NDEC)

__global__ void prep_all(const float* __restrict__ W0, const float* __restrict__ W1,
                         const float* __restrict__ Wtr, const float* __restrict__ Wc,
                         const float* __restrict__ x,
                         const float* __restrict__ a, const float* __restrict__ b){
  int i = blockIdx.x*blockDim.x + threadIdx.x;
  if (i < NW0){
    g_w0h[i] = __float2half_rn(W0[i]);
  } else if (i < NW0+NW1){
    int k = i - NW0;
    g_w1h[k] = __float2half_rn(W1[k]);
  } else if (i < NW0+NW1+NWP){
    int idx = i - NW0 - NW1;
    int l = idx / (128*D_);
    int rem = idx % (128*D_);
    int row = rem / D_, k = rem % D_;
    float v = (row < 64) ? Wtr[((size_t)l*64+row)*D_+k] : Wc[((size_t)l*64+row-64)*D_+k];
    g_wph[idx] = __float2half_rn(v);
  } else if (i < NW0+NW1+NWP+NX){
    int k = i - NW0 - NW1 - NWP;
    float v = x[k];
    g_x[k] = v;
    g_xh[k] = __float2half_rn(v);
  } else if (i < NPREP){
    int k = i - NW0 - NW1 - NWP - NX;
    int l = k / NCH_;
    int ch = k % NCH_;
    int i0 = ch / CC_, j0 = ch % CC_;
    double ai = fabs((double)a[l*TR_+i0]);
    double bj = (double)b[l*CC_+j0];
    double rho = exp(-ai);
    double sb, cb; sincos(bj, &sb, &cb);
    g_dec[k] = make_float2((float)(rho*cb), (float)(rho*sb));
    double rhoL = exp(-ai*(double)CHUNK_);
    double sL, cL; sincos(bj*(double)CHUNK_, &sL, &cL);
    g_decL[k] = make_float2((float)(rhoL*cL), (float)(rhoL*sL));
  }
}

// ================= 1-term fp16 GEMM with uneven split-K =================
#define PADH 72
#define TILEH (128*PADH)
#define STAGE1 (2*TILEH)
#define GEMM1_SMEM (3*STAGE1*2)        // 110592 B

__device__ __forceinline__ void stage_load1(
    __half* s, const __half* Ah, const __half* Bh,
    int bm, int bn, int K, int k0, int tid)
{
  const __half* src[2] = {Ah, Bh};
  #pragma unroll
  for (int t=0;t<2;t++){
    int rb = (t==0)? bm : bn;
    #pragma unroll
    for (int q=0;q<4;q++){
      int chunk = tid + q*256;
      int row = chunk>>3, cc = chunk&7;
      uint32_t so = sptr(s + t*TILEH + row*PADH + cc*8);
      cp16(so, src[t] + (size_t)(rb+row)*K + k0 + cc*8);
    }
  }
}

__global__ void __launch_bounds__(256, 2)
gemm1(const __half* __restrict__ Ah, const __half* __restrict__ Bh,
      float* __restrict__ Cbase, int K, int Nc, int nsplit)
{
  extern __shared__ __half smh[];
  const int tid = threadIdx.x;
  const int wid = tid>>5, lane = tid&31;
  const int bm = blockIdx.y*128, bn = blockIdx.x*128;
  const int kz = blockIdx.z;
  // uneven split of (K/64) iterations across nsplit parts
  const int tot = K>>6;
  const int base_it = tot / nsplit;
  const int extra = tot - base_it*nsplit;
  const int KT = base_it + (kz < extra ? 1 : 0);
  const int it0 = kz*base_it + (kz < extra ? kz : extra);
  const int kbase = it0<<6;
  float* C = Cbase + (size_t)kz * T_ * D_;
  const int wm = (wid>>1)*32;
  const int wn = (wid&1)*64;

  float acc[2][8][4];
  #pragma unroll
  for (int i=0;i<2;i++)
    #pragma unroll
    for (int j=0;j<8;j++)
      #pragma unroll
      for (int q=0;q<4;q++) acc[i][j][q]=0.f;

  stage_load1(smh, Ah, Bh, bm, bn, K, kbase, tid);
  CP_COMMIT();
  if (KT > 1){
    stage_load1(smh + STAGE1, Ah, Bh, bm, bn, K, kbase + 64, tid);
    CP_COMMIT();
  }

  const int arow = lane & 15;
  const int acol8 = (lane>>4)*8;
  const int brow = (lane&7) + ((lane>>4)<<3);
  const int bsel = ((lane>>3)&1)*8;

  int bufc = 0;
  for (int c=0; c<KT; c++){
    if (c+1 < KT) { CP_WAIT(1); } else { CP_WAIT(0); }
    __syncthreads();

    __half* s = smh + bufc*STAGE1;
    const uint32_t sAh = sptr(s);
    const uint32_t sBh = sAh + TILEH*2;

    #pragma unroll
    for (int ks=0; ks<4; ks++){
      uint32_t ah[2][4], bh[4][4];
      #pragma unroll
      for (int mi=0; mi<2; mi++){
        uint32_t off = (uint32_t)((wm + mi*16 + arow)*PADH + ks*16 + acol8)*2;
        ldsm4(ah[mi], sAh + off);
      }
      #pragma unroll
      for (int p=0; p<4; p++){
        uint32_t off = (uint32_t)((wn + p*16 + brow)*PADH + ks*16 + bsel)*2;
        ldsm4(bh[p], sBh + off);
      }
      #pragma unroll
      for (int mi=0; mi<2; mi++)
        #pragma unroll
        for (int p=0; p<4; p++)
          #pragma unroll
          for (int h=0; h<2; h++)
            mma_h(acc[mi][p*2+h], ah[mi], &bh[p][h*2]);
    }

    if (c+2 < KT){
      int buf2 = bufc + 2; if (buf2 >= 3) buf2 -= 3;
      stage_load1(smh + buf2*STAGE1, Ah, Bh, bm, bn, K, kbase + (c+2)*64, tid);
      CP_COMMIT();
    }
    bufc++; if (bufc == 3) bufc = 0;
  }

  #pragma unroll
  for (int mi=0; mi<2; mi++){
    const int r0 = bm + wm + mi*16 + (lane>>2);
    const int c0 = bn + wn + (lane&3)*2;
    #pragma unroll
    for (int ni=0; ni<8; ni++){
      *(float2*)(C + (size_t)r0*Nc + c0 + ni*8)     = make_float2(acc[mi][ni][0], acc[mi][ni][1]);
      *(float2*)(C + (size_t)(r0+8)*Nc + c0 + ni*8) = make_float2(acc[mi][ni][2], acc[mi][ni][3]);
    }
  }
}

// ================= fused projection + uv (1-term) =================
#define PPADH 72
#define PA_TILE (64*PPADH)
#define PB_TILE (128*PPADH)
#define PSTAGE (PA_TILE + PB_TILE)
#define PROJ_SMEM (2*PSTAGE*2)

__device__ __forceinline__ void stage_load_proj(
    __half* s, const __half* Ah, const __half* Bh,
    int bm, int K, int k0, int tid)
{
  #pragma unroll
  for (int q=0;q<2;q++){
    int chunk = tid + q*256;
    int row = chunk>>3, cc = chunk&7;
    uint32_t so = sptr(s + row*PPADH + cc*8);
    cp16(so, Ah + (size_t)(bm+row)*K + k0 + cc*8);
  }
  #pragma unroll
  for (int q=0;q<4;q++){
    int chunk = tid + q*256;
    int row = chunk>>3, cc = chunk&7;
    uint32_t so = sptr(s + PA_TILE + row*PPADH + cc*8);
    cp16(so, Bh + (size_t)row*K + k0 + cc*8);
  }
}

__global__ void __launch_bounds__(256)
proj_uv(const __half* __restrict__ Ah, const __half* __restrict__ Bh)
{
  extern __shared__ __half smh[];
  __shared__ float ssum[4][64];
  __shared__ float sscale[64];
  const int tid = threadIdx.x;
  const int wid = tid>>5, lane = tid&31;
  const int bm = blockIdx.y*64;
  const int wm = (wid&1)*32;
  const int wn = (wid>>1)*32;
  const int K = D_;
  const int KT = K>>6;

  float acc[2][4][4];
  #pragma unroll
  for (int i=0;i<2;i++)
    #pragma unroll
    for (int j=0;j<4;j++)
      #pragma unroll
      for (int q=0;q<4;q++) acc[i][j][q]=0.f;

  stage_load_proj(smh, Ah, Bh, bm, K, 0, tid);
  CP_COMMIT();

  const int arow = lane & 15;
  const int acol8 = (lane>>4)*8;
  const int brow = (lane&7) + ((lane>>4)<<3);
  const int bsel = ((lane>>3)&1)*8;

  for (int c=0; c<KT; c++){
    if (c+1 < KT){
      stage_load_proj(smh + ((c+1)&1)*PSTAGE, Ah, Bh, bm, K, (c+1)*64, tid);
      CP_COMMIT();
      CP_WAIT(1);
    } else {
      CP_WAIT(0);
    }
    __syncthreads();

    __half* s = smh + (c&1)*PSTAGE;
    const uint32_t sAh = sptr(s);
    const uint32_t sBh = sAh + PA_TILE*2;

    #pragma unroll
    for (int ks=0; ks<4; ks++){
      uint32_t ah[2][4], bh[2][4];
      #pragma unroll
      for (int mi=0; mi<2; mi++){
        uint32_t off = (uint32_t)((wm + mi*16 + arow)*PPADH + ks*16 + acol8)*2;
        ldsm4(ah[mi], sAh + off);
      }
      #pragma unroll
      for (int p=0; p<2; p++){
        uint32_t off = (uint32_t)((wn + p*16 + brow)*PPADH + ks*16 + bsel)*2;
        ldsm4(bh[p], sBh + off);
      }
      #pragma unroll
      for (int mi=0; mi<2; mi++)
        #pragma unroll
        for (int p=0; p<2; p++)
          #pragma unroll
          for (int h=0; h<2; h++)
            mma_h(acc[mi][p*2+h], ah[mi], &bh[p][h*2]);
    }
    __syncthreads();
  }

  const int colblk = wid>>1;
  #pragma unroll
  for (int mi=0; mi<2; mi++){
    #pragma unroll
    for (int qh=0; qh<2; qh++){
      float sv = 0.f;
      #pragma unroll
      for (int ni=0; ni<4; ni++)
        sv += fabsf(acc[mi][ni][qh*2]) + fabsf(acc[mi][ni][qh*2+1]);
      sv += __shfl_xor_sync(0xffffffffu, sv, 1);
      sv += __shfl_xor_sync(0xffffffffu, sv, 2);
      if ((lane&3)==0)
        ssum[colblk][wm + mi*16 + qh*8 + (lane>>2)] = sv;
    }
  }
  __syncthreads();
  if (tid < 64){
    float str = ssum[0][tid] + ssum[1][tid];
    float sct = ssum[2][tid] + ssum[3][tid];
    sscale[tid] = __fdividef(1.f, 1e-8f + str*sct);
  }
  __syncthreads();
  #pragma unroll
  for (int mi=0; mi<2; mi++){
    #pragma unroll
    for (int ni=0; ni<4; ni++){
      #pragma unroll
      for (int q=0; q<4; q++){
        int rloc = wm + mi*16 + (q>>1)*8 + (lane>>2);
        int t = bm + rloc;
        int col = wn + (lane&3)*2 + ni*8 + (q&1);
        float vabs = fabsf(acc[mi][ni][q]);
        if (col < 64) g_u[t*TR_ + col] = vabs;
        else          g_v[t*CC_ + col - 64] = vabs * sscale[rloc];
      }
    }
  }
}

// ---------------- scan ----------------
__global__ void scan_passA(const unsigned* __restrict__ start, int layer){
  const int i = blockIdx.y;
  const int c = blockIdx.x;
  const int j = threadIdx.x;
  const int ch = i*CC_+j;
  float2 d = g_dec[layer*NCH_ + ch];
  const float dre = d.x, dim = d.y;
  float sre=0.f, sim=0.f;
  int reset = 0;
  const int t0 = c*CHUNK_;
  #pragma unroll 4
  for (int t=t0; t<t0+CHUNK_; t++){
    if (start[t]){ sre=0.f; sim=0.f; reset=1; }
    float p = g_u[t*TR_+i]*g_v[t*CC_+j];
    float nre = fmaf(sre,dre, fmaf(-sim,dim,p));
    float nim = fmaf(sre,dim, sim*dre);
    sre=nre; sim=nim;
  }
  g_Bend[c*NCH_+ch]=make_float2(sre,sim);
  float2 A = make_float2(0.f, 0.f);
  if (!reset) A = g_decL[layer*NCH_ + ch];
  g_Amat[c*NCH_+ch]=A;
}

// pass C with folded chunk-combine + slim feature math
__global__ void scan_passC(const unsigned* __restrict__ start,
                           const float* __restrict__ state, int layer){
  const int i = blockIdx.y, c = blockIdx.x, j = threadIdx.x;
  const int ch = i*CC_+j;
  float2 d = g_dec[layer*NCH_ + ch];
  const float dre = d.x, dim = d.y;
  float sre = state[layer*NCH_ + ch];
  float sim = 0.f;
  for (int cc=0; cc<c; cc++){
    float2 A = g_Amat[cc*NCH_+ch];
    float2 B = g_Bend[cc*NCH_+ch];
    float nr = A.x*sre - A.y*sim + B.x;
    float ni = A.x*sim + A.y*sre + B.y;
    sre=nr; sim=ni;
  }
  const int t0=c*CHUNK_;
  #pragma unroll 4
  for (int t=t0;t<t0+CHUNK_;t++){
    if (start[t]){ sre=0.f; sim=0.f; }
    float p = g_u[t*TR_+i]*g_v[t*CC_+j];
    float nre = fmaf(sre,dre, fmaf(-sim,dim,p));
    float nim = fmaf(sre,dim, sim*dre);
    sre=nre; sim=nim;
    float r2 = fmaf(sre,sre, sim*sim);
    float fs, fc;
    if (r2 > 1e-24f){
      float ir = rsqrtf(r2);
      float rr = r2*ir;               // sqrt(r2)
      float f = __logf(1.f + rr)*ir;  // log1p(r)/r
      fs = f*sim; fc = f*sre;
    } else {
      fs = sim; fc = sre;             // f -> 1
    }
    size_t o0 = (size_t)t*F_ + ch;
    g_sclh[o0]        = __float2half_rn(fs);
    g_sclh[o0 + NCH_] = __float2half_rn(fc);
  }
}

// ================= LayerNorm + leaky ReLU =================
__device__ __forceinline__ void reduce2(float &s, float &ss){
  __shared__ float sh[8], sh2[8];
  int lane = threadIdx.x & 31, w = threadIdx.x >> 5;
  #pragma unroll
  for (int o=16;o>0;o>>=1){
    s  += __shfl_down_sync(0xffffffffu, s,  o);
    ss += __shfl_down_sync(0xffffffffu, ss, o);
  }
  if (lane==0){ sh[w]=s; sh2[w]=ss; }
  __syncthreads();
  if (w==0){
    s  = (lane<8)? sh[lane]  : 0.f;
    ss = (lane<8)? sh2[lane] : 0.f;
    #pragma unroll
    for (int o=4;o>0;o>>=1){
      s  += __shfl_down_sync(0xffffffffu, s,  o);
      ss += __shfl_down_sync(0xffffffffu, ss, o);
    }
    if (lane==0){ sh[0]=s; sh2[0]=ss; }
  }
  __syncthreads();
  s = sh[0]; ss = sh2[0];
}

__global__ void ln_leaky(const float* __restrict__ zin, int nparts,
                         const float* __restrict__ bias,
                         const float* __restrict__ gamma, const float* __restrict__ beta,
                         float* __restrict__ zout, float* __restrict__ xacc,
                         __half* __restrict__ zh, __half* __restrict__ xh){
  const int t = blockIdx.x;
  const int tid = threadIdx.x;
  float v0 = bias[tid];
  float v1 = bias[256+tid];
  for (int p=0; p<nparts; p++){
    v0 += zin[(size_t)p*T_*D_ + t*D_ + tid];
    v1 += zin[(size_t)p*T_*D_ + t*D_ + 256 + tid];
  }
  float s = v0+v1;
  float ss = v0*v0 + v1*v1;
  reduce2(s, ss);
  float m = s * (1.f/512.f);
  float var = ss * (1.f/512.f) - m*m;
  float rinv = rsqrtf(var + 1e-5f);
  float y0 = (v0 - m)*rinv*gamma[tid]     + beta[tid];
  float y1 = (v1 - m)*rinv*gamma[256+tid] + beta[256+tid];
  y0 = (y0 > 0.f) ? y0 : 0.01f*y0;
  y1 = (y1 > 0.f) ? y1 : 0.01f*y1;
  if (zout){
    zout[t*D_ + tid]       = y0;
    zout[t*D_ + 256 + tid] = y1;
  }
  if (xacc){
    float x0 = xacc[t*D_ + tid]       + y0;
    float x1 = xacc[t*D_ + 256 + tid] + y1;
    xacc[t*D_ + tid]       = x0;
    xacc[t*D_ + 256 + tid] = x1;
    if (xh){
      xh[t*D_ + tid]       = __float2half_rn(x0);
      xh[t*D_ + 256 + tid] = __float2half_rn(x1);
    }
  }
  if (zh){
    zh[t*D_ + tid]       = __float2half_rn(y0);
    zh[t*D_ + 256 + tid] = __float2half_rn(y1);
  }
}

// ================= launcher =================
extern "C" void kernel_launch(void* const* d_in, const int* in_sizes, int n_in,
                              void* d_out, int out_size) {
  const float*    x     = (const float*)d_in[0];
  const float*    state = (const float*)d_in[1];
  const unsigned* start = (const unsigned*)d_in[2];
  const float*    Wtr   = (const float*)d_in[3];
  const float*    Wc    = (const float*)d_in[4];
  const float*    a     = (const float*)d_in[5];
  const float*    b     = (const float*)d_in[6];
  const float*    W0    = (const float*)d_in[7];
  const float*    b0    = (const float*)d_in[8];
  const float*    g0    = (const float*)d_in[9];
  const float*    beta0 = (const float*)d_in[10];
  const float*    W1    = (const float*)d_in[11];
  const float*    b1    = (const float*)d_in[12];
  const float*    g1    = (const float*)d_in[13];
  const float*    beta1 = (const float*)d_in[14];
  float* out = (float*)d_out;

  float *px, *php, *pzt;
  __half *psh, *pw0h, *pw1h, *pwph, *pz0h, *pxh;
  cudaGetSymbolAddress((void**)&px,    g_x);
  cudaGetSymbolAddress((void**)&php,   g_hp);
  cudaGetSymbolAddress((void**)&pzt,   g_ztmp);
  cudaGetSymbolAddress((void**)&psh,   g_sclh);
  cudaGetSymbolAddress((void**)&pw0h,  g_w0h);
  cudaGetSymbolAddress((void**)&pw1h,  g_w1h);
  cudaGetSymbolAddress((void**)&pwph,  g_wph);
  cudaGetSymbolAddress((void**)&pz0h,  g_z0h);
  cudaGetSymbolAddress((void**)&pxh,   g_xh);

  cudaFuncSetAttribute(gemm1,   cudaFuncAttributeMaxDynamicSharedMemorySize, GEMM1_SMEM);
  cudaFuncSetAttribute(proj_uv, cudaFuncAttributeMaxDynamicSharedMemorySize, PROJ_SMEM);

  prep_all<<<(NPREP + 255)/256, 256>>>(W0, W1, Wtr, Wc, x, a, b);

  for (int l=0; l<L_; l++){
    proj_uv<<<dim3(1, T_/64), 256, PROJ_SMEM>>>(pxh, pwph + (size_t)l*128*D_);

    scan_passA<<<dim3(NCHUNK_, TR_), CC_>>>(start, l);
    scan_passC<<<dim3(NCHUNK_, TR_), CC_>>>(start, state, l);

    // h = scaled @ W0^T  (M=4096, N=512, K=8192), uneven split-K=9 -> 1152 CTAs
    gemm1<<<dim3(D_/128, T_/128, NSPLIT0_), 256, GEMM1_SMEM>>>(
        psh, pw0h + (size_t)l*D_*F_, php, F_, D_, NSPLIT0_);
    ln_leaky<<<T_, 256>>>(php, NSPLIT0_, b0 + l*D_, g0 + l*D_, beta0 + l*D_,
                          nullptr, nullptr, pz0h, nullptr);

    // h = z0 @ W1^T  (M=4096, N=512, K=512), split-K=2 -> 256 CTAs
    gemm1<<<dim3(D_/128, T_/128, NSPLIT1_), 256, GEMM1_SMEM>>>(
        pz0h, pw1h + (size_t)l*D_*D_, php, D_, D_, NSPLIT1_);
    float* zo = (l == L_-1) ? out : pzt;
    bool last = (l == L_-1);
    ln_leaky<<<T_, 256>>>(php, NSPLIT1_, b1 + l*D_, g1 + l*D_, beta1 + l*D_,
                          zo, px, nullptr, last ? nullptr : pxh);
  }
}

// round 13
// speedup vs baseline: 1.4279x; 1.4279x over previous
#include <cuda_runtime.h>
#include <cuda_fp16.h>
#include <math.h>
#include <stdint.h>

#define T_ 4096
#define D_ 512
#define TR_ 64
#define CC_ 64
#define L_ 3
#define F_ 8192
#define NCH_ 4096
#define NCHUNK_ 64
#define CHUNK_ 64
#define NSPLIT0_ 4
#define NSPLIT1_ 2

// ---------------- scratch ----------------
__device__ float g_x[T_*D_];
__device__ float g_u[T_*TR_];
__device__ float g_v[T_*CC_];
__device__ float2 g_Bend[NCHUNK_*NCH_];
__device__ float2 g_Amat[NCHUNK_*NCH_];
__device__ float2 g_dec[L_*NCH_];
__device__ float2 g_decL[L_*NCH_];
__device__ float g_hp[NSPLIT0_][T_*D_];
__device__ float g_ztmp[T_*D_];
__device__ __half g_sclh[(size_t)T_*F_];
__device__ __half g_w0h[L_*D_*F_];
__device__ __half g_w1h[L_*D_*D_];
__device__ __half g_wph[L_*128*D_];
__device__ __half g_z0h[T_*D_];
__device__ __half g_xh[T_*D_];

// ---------------- low-level helpers (baseline PTX @ compute_103) ----------------
__device__ __forceinline__ uint32_t sptr(const void* p){
  return (uint32_t)__cvta_generic_to_shared(p);
}
__device__ __forceinline__ void cp16(uint32_t s, const void* g){
  asm volatile("cp.async.cg.shared.global [%0], [%1], 16;" :: "r"(s), "l"(g));
}
#define CP_COMMIT() asm volatile("cp.async.commit_group;" ::: "memory")
#define CP_WAIT(n)  asm volatile("cp.async.wait_group %0;" :: "n"(n) : "memory")

__device__ __forceinline__ void ldsm4(uint32_t* r, uint32_t a){
  asm volatile("ldmatrix.sync.aligned.m8n8.x4.shared.b16 {%0,%1,%2,%3}, [%4];"
    : "=r"(r[0]),"=r"(r[1]),"=r"(r[2]),"=r"(r[3]) : "r"(a));
}
__device__ __forceinline__ void mma_h(float* d, const uint32_t* a, const uint32_t* b){
  asm volatile("mma.sync.aligned.m16n8k16.row.col.f32.f16.f16.f32 "
    "{%0,%1,%2,%3}, {%4,%5,%6,%7}, {%8,%9}, {%0,%1,%2,%3};"
    : "+f"(d[0]),"+f"(d[1]),"+f"(d[2]),"+f"(d[3])
    : "r"(a[0]),"r"(a[1]),"r"(a[2]),"r"(a[3]), "r"(b[0]),"r"(b[1]));
}

// ---------------- merged prep kernel ----------------
#define NW0 (L_*D_*F_)
#define NW1 (L_*D_*D_)
#define NWP (L_*128*D_)
#define NX  (T_*D_)
#define NDEC (L_*NCH_)
#define NPREP (NW0+NW1+NWP+NX+NDEC)

__global__ void prep_all(const float* __restrict__ W0, const float* __restrict__ W1,
                         const float* __restrict__ Wtr, const float* __restrict__ Wc,
                         const float* __restrict__ x,
                         const float* __restrict__ a, const float* __restrict__ b){
  int i = blockIdx.x*blockDim.x + threadIdx.x;
  if (i < NW0){
    g_w0h[i] = __float2half_rn(W0[i]);
  } else if (i < NW0+NW1){
    int k = i - NW0;
    g_w1h[k] = __float2half_rn(W1[k]);
  } else if (i < NW0+NW1+NWP){
    int idx = i - NW0 - NW1;
    int l = idx / (128*D_);
    int rem = idx % (128*D_);
    int row = rem / D_, k = rem % D_;
    float v = (row < 64) ? Wtr[((size_t)l*64+row)*D_+k] : Wc[((size_t)l*64+row-64)*D_+k];
    g_wph[idx] = __float2half_rn(v);
  } else if (i < NW0+NW1+NWP+NX){
    int k = i - NW0 - NW1 - NWP;
    float v = x[k];
    g_x[k] = v;
    g_xh[k] = __float2half_rn(v);
  } else if (i < NPREP){
    int k = i - NW0 - NW1 - NWP - NX;
    int l = k / NCH_;
    int ch = k % NCH_;
    int i0 = ch / CC_, j0 = ch % CC_;
    double ai = fabs((double)a[l*TR_+i0]);
    double bj = (double)b[l*CC_+j0];
    double rho = exp(-ai);
    double sb, cb; sincos(bj, &sb, &cb);
    g_dec[k] = make_float2((float)(rho*cb), (float)(rho*sb));
    double rhoL = exp(-ai*(double)CHUNK_);
    double sL, cL; sincos(bj*(double)CHUNK_, &sL, &cL);
    g_decL[k] = make_float2((float)(rhoL*cL), (float)(rhoL*sL));
  }
}

// ================= 1-term fp16 GEMM with split-K (even) =================
#define PADH 72
#define TILEH (128*PADH)
#define STAGE1 (2*TILEH)
#define GEMM1_SMEM (3*STAGE1*2)        // 110592 B

__device__ __forceinline__ void stage_load1(
    __half* s, const __half* Ah, const __half* Bh,
    int bm, int bn, int K, int k0, int tid)
{
  const __half* src[2] = {Ah, Bh};
  #pragma unroll
  for (int t=0;t<2;t++){
    int rb = (t==0)? bm : bn;
    #pragma unroll
    for (int q=0;q<4;q++){
      int chunk = tid + q*256;
      int row = chunk>>3, cc = chunk&7;
      uint32_t so = sptr(s + t*TILEH + row*PADH + cc*8);
      cp16(so, src[t] + (size_t)(rb+row)*K + k0 + cc*8);
    }
  }
}

__global__ void __launch_bounds__(256, 2)
gemm1(const __half* __restrict__ Ah, const __half* __restrict__ Bh,
      float* __restrict__ Cbase, int K, int KS, int Nc)
{
  extern __shared__ __half smh[];
  const int tid = threadIdx.x;
  const int wid = tid>>5, lane = tid&31;
  const int bm = blockIdx.y*128, bn = blockIdx.x*128;
  const int kz = blockIdx.z;
  const int kbase = kz * KS;
  float* C = Cbase + (size_t)kz * T_ * D_;
  const int wm = (wid>>1)*32;
  const int wn = (wid&1)*64;
  const int KT = KS>>6;

  float acc[2][8][4];
  #pragma unroll
  for (int i=0;i<2;i++)
    #pragma unroll
    for (int j=0;j<8;j++)
      #pragma unroll
      for (int q=0;q<4;q++) acc[i][j][q]=0.f;

  stage_load1(smh, Ah, Bh, bm, bn, K, kbase, tid);
  CP_COMMIT();
  if (KT > 1){
    stage_load1(smh + STAGE1, Ah, Bh, bm, bn, K, kbase + 64, tid);
    CP_COMMIT();
  }

  const int arow = lane & 15;
  const int acol8 = (lane>>4)*8;
  const int brow = (lane&7) + ((lane>>4)<<3);
  const int bsel = ((lane>>3)&1)*8;

  int bufc = 0;
  for (int c=0; c<KT; c++){
    if (c+1 < KT) { CP_WAIT(1); } else { CP_WAIT(0); }
    __syncthreads();

    __half* s = smh + bufc*STAGE1;
    const uint32_t sAh = sptr(s);
    const uint32_t sBh = sAh + TILEH*2;

    #pragma unroll
    for (int ks=0; ks<4; ks++){
      uint32_t ah[2][4], bh[4][4];
      #pragma unroll
      for (int mi=0; mi<2; mi++){
        uint32_t off = (uint32_t)((wm + mi*16 + arow)*PADH + ks*16 + acol8)*2;
        ldsm4(ah[mi], sAh + off);
      }
      #pragma unroll
      for (int p=0; p<4; p++){
        uint32_t off = (uint32_t)((wn + p*16 + brow)*PADH + ks*16 + bsel)*2;
        ldsm4(bh[p], sBh + off);
      }
      #pragma unroll
      for (int mi=0; mi<2; mi++)
        #pragma unroll
        for (int p=0; p<4; p++)
          #pragma unroll
          for (int h=0; h<2; h++)
            mma_h(acc[mi][p*2+h], ah[mi], &bh[p][h*2]);
    }

    if (c+2 < KT){
      int buf2 = bufc + 2; if (buf2 >= 3) buf2 -= 3;
      stage_load1(smh + buf2*STAGE1, Ah, Bh, bm, bn, K, kbase + (c+2)*64, tid);
      CP_COMMIT();
    }
    bufc++; if (bufc == 3) bufc = 0;
  }

  #pragma unroll
  for (int mi=0; mi<2; mi++){
    const int r0 = bm + wm + mi*16 + (lane>>2);
    const int c0 = bn + wn + (lane&3)*2;
    #pragma unroll
    for (int ni=0; ni<8; ni++){
      *(float2*)(C + (size_t)r0*Nc + c0 + ni*8)     = make_float2(acc[mi][ni][0], acc[mi][ni][1]);
      *(float2*)(C + (size_t)(r0+8)*Nc + c0 + ni*8) = make_float2(acc[mi][ni][2], acc[mi][ni][3]);
    }
  }
}

// ================= fused projection + uv (1-term) =================
#define PPADH 72
#define PA_TILE (64*PPADH)
#define PB_TILE (128*PPADH)
#define PSTAGE (PA_TILE + PB_TILE)
#define PROJ_SMEM (2*PSTAGE*2)

__device__ __forceinline__ void stage_load_proj(
    __half* s, const __half* Ah, const __half* Bh,
    int bm, int K, int k0, int tid)
{
  #pragma unroll
  for (int q=0;q<2;q++){
    int chunk = tid + q*256;
    int row = chunk>>3, cc = chunk&7;
    uint32_t so = sptr(s + row*PPADH + cc*8);
    cp16(so, Ah + (size_t)(bm+row)*K + k0 + cc*8);
  }
  #pragma unroll
  for (int q=0;q<4;q++){
    int chunk = tid + q*256;
    int row = chunk>>3, cc = chunk&7;
    uint32_t so = sptr(s + PA_TILE + row*PPADH + cc*8);
    cp16(so, Bh + (size_t)row*K + k0 + cc*8);
  }
}

__global__ void __launch_bounds__(256)
proj_uv(const __half* __restrict__ Ah, const __half* __restrict__ Bh)
{
  extern __shared__ __half smh[];
  __shared__ float ssum[4][64];
  __shared__ float sscale[64];
  const int tid = threadIdx.x;
  const int wid = tid>>5, lane = tid&31;
  const int bm = blockIdx.y*64;
  const int wm = (wid&1)*32;
  const int wn = (wid>>1)*32;
  const int K = D_;
  const int KT = K>>6;

  float acc[2][4][4];
  #pragma unroll
  for (int i=0;i<2;i++)
    #pragma unroll
    for (int j=0;j<4;j++)
      #pragma unroll
      for (int q=0;q<4;q++) acc[i][j][q]=0.f;

  stage_load_proj(smh, Ah, Bh, bm, K, 0, tid);
  CP_COMMIT();

  const int arow = lane & 15;
  const int acol8 = (lane>>4)*8;
  const int brow = (lane&7) + ((lane>>4)<<3);
  const int bsel = ((lane>>3)&1)*8;

  for (int c=0; c<KT; c++){
    if (c+1 < KT){
      stage_load_proj(smh + ((c+1)&1)*PSTAGE, Ah, Bh, bm, K, (c+1)*64, tid);
      CP_COMMIT();
      CP_WAIT(1);
    } else {
      CP_WAIT(0);
    }
    __syncthreads();

    __half* s = smh + (c&1)*PSTAGE;
    const uint32_t sAh = sptr(s);
    const uint32_t sBh = sAh + PA_TILE*2;

    #pragma unroll
    for (int ks=0; ks<4; ks++){
      uint32_t ah[2][4], bh[2][4];
      #pragma unroll
      for (int mi=0; mi<2; mi++){
        uint32_t off = (uint32_t)((wm + mi*16 + arow)*PPADH + ks*16 + acol8)*2;
        ldsm4(ah[mi], sAh + off);
      }
      #pragma unroll
      for (int p=0; p<2; p++){
        uint32_t off = (uint32_t)((wn + p*16 + brow)*PPADH + ks*16 + bsel)*2;
        ldsm4(bh[p], sBh + off);
      }
      #pragma unroll
      for (int mi=0; mi<2; mi++)
        #pragma unroll
        for (int p=0; p<2; p++)
          #pragma unroll
          for (int h=0; h<2; h++)
            mma_h(acc[mi][p*2+h], ah[mi], &bh[p][h*2]);
    }
    __syncthreads();
  }

  const int colblk = wid>>1;
  #pragma unroll
  for (int mi=0; mi<2; mi++){
    #pragma unroll
    for (int qh=0; qh<2; qh++){
      float sv = 0.f;
      #pragma unroll
      for (int ni=0; ni<4; ni++)
        sv += fabsf(acc[mi][ni][qh*2]) + fabsf(acc[mi][ni][qh*2+1]);
      sv += __shfl_xor_sync(0xffffffffu, sv, 1);
      sv += __shfl_xor_sync(0xffffffffu, sv, 2);
      if ((lane&3)==0)
        ssum[colblk][wm + mi*16 + qh*8 + (lane>>2)] = sv;
    }
  }
  __syncthreads();
  if (tid < 64){
    float str = ssum[0][tid] + ssum[1][tid];
    float sct = ssum[2][tid] + ssum[3][tid];
    sscale[tid] = __fdividef(1.f, 1e-8f + str*sct);
  }
  __syncthreads();
  #pragma unroll
  for (int mi=0; mi<2; mi++){
    #pragma unroll
    for (int ni=0; ni<4; ni++){
      #pragma unroll
      for (int q=0; q<4; q++){
        int rloc = wm + mi*16 + (q>>1)*8 + (lane>>2);
        int t = bm + rloc;
        int col = wn + (lane&3)*2 + ni*8 + (q&1);
        float vabs = fabsf(acc[mi][ni][q]);
        if (col < 64) g_u[t*TR_ + col] = vabs;
        else          g_v[t*CC_ + col - 64] = vabs * sscale[rloc];
      }
    }
  }
}

// ---------------- scan: SMEM-staged u + start ----------------
__global__ void scan_passA(const unsigned* __restrict__ start, int layer){
  const int i = blockIdx.y;
  const int c = blockIdx.x;
  const int j = threadIdx.x;
  const int ch = i*CC_+j;
  const int t0 = c*CHUNK_;
  __shared__ float su[CHUNK_];
  __shared__ unsigned sst[CHUNK_];
  su[j]  = g_u[(t0+j)*TR_ + i];
  sst[j] = start[t0+j];
  __syncthreads();
  float2 d = g_dec[layer*NCH_ + ch];
  const float dre = d.x, dim = d.y;
  float sre=0.f, sim=0.f;
  int reset = 0;
  #pragma unroll 4
  for (int tt=0; tt<CHUNK_; tt++){
    if (sst[tt]){ sre=0.f; sim=0.f; reset=1; }
    float p = su[tt]*g_v[(t0+tt)*CC_+j];
    float nre = fmaf(sre,dre, fmaf(-sim,dim,p));
    float nim = fmaf(sre,dim, sim*dre);
    sre=nre; sim=nim;
  }
  g_Bend[c*NCH_+ch]=make_float2(sre,sim);
  float2 A = make_float2(0.f, 0.f);
  if (!reset) A = g_decL[layer*NCH_ + ch];
  g_Amat[c*NCH_+ch]=A;
}

// pass C with folded chunk-combine, SMEM-staged u + start
__global__ void scan_passC(const unsigned* __restrict__ start,
                           const float* __restrict__ state, int layer){
  const int i = blockIdx.y, c = blockIdx.x, j = threadIdx.x;
  const int ch = i*CC_+j;
  const int t0 = c*CHUNK_;
  __shared__ float su[CHUNK_];
  __shared__ unsigned sst[CHUNK_];
  su[j]  = g_u[(t0+j)*TR_ + i];
  sst[j] = start[t0+j];
  __syncthreads();
  float2 d = g_dec[layer*NCH_ + ch];
  const float dre = d.x, dim = d.y;
  float sre = state[layer*NCH_ + ch];
  float sim = 0.f;
  for (int cc=0; cc<c; cc++){
    float2 A = g_Amat[cc*NCH_+ch];
    float2 B = g_Bend[cc*NCH_+ch];
    float nr = A.x*sre - A.y*sim + B.x;
    float ni = A.x*sim + A.y*sre + B.y;
    sre=nr; sim=ni;
  }
  #pragma unroll 4
  for (int tt=0; tt<CHUNK_; tt++){
    if (sst[tt]){ sre=0.f; sim=0.f; }
    float p = su[tt]*g_v[(t0+tt)*CC_+j];
    float nre = fmaf(sre,dre, fmaf(-sim,dim,p));
    float nim = fmaf(sre,dim, sim*dre);
    sre=nre; sim=nim;
    float r2 = fmaf(sre,sre, sim*sim);
    float f;
    if (r2 > 1e-24f){
      float rr = sqrtf(r2);
      f = __fdividef(log1pf(rr), rr);
    } else {
      f = 1.f;
    }
    size_t o0 = (size_t)(t0+tt)*F_ + ch;
    g_sclh[o0]        = __float2half_rn(f*sim);
    g_sclh[o0 + NCH_] = __float2half_rn(f*sre);
  }
}

// ================= LayerNorm + leaky ReLU =================
__device__ __forceinline__ void reduce2(float &s, float &ss){
  __shared__ float sh[8], sh2[8];
  int lane = threadIdx.x & 31, w = threadIdx.x >> 5;
  #pragma unroll
  for (int o=16;o>0;o>>=1){
    s  += __shfl_down_sync(0xffffffffu, s,  o);
    ss += __shfl_down_sync(0xffffffffu, ss, o);
  }
  if (lane==0){ sh[w]=s; sh2[w]=ss; }
  __syncthreads();
  if (w==0){
    s  = (lane<8)? sh[lane]  : 0.f;
    ss = (lane<8)? sh2[lane] : 0.f;
    #pragma unroll
    for (int o=4;o>0;o>>=1){
      s  += __shfl_down_sync(0xffffffffu, s,  o);
      ss += __shfl_down_sync(0xffffffffu, ss, o);
    }
    if (lane==0){ sh[0]=s; sh2[0]=ss; }
  }
  __syncthreads();
  s = sh[0]; ss = sh2[0];
}

__global__ void ln_leaky(const float* __restrict__ zin, int nparts,
                         const float* __restrict__ bias,
                         const float* __restrict__ gamma, const float* __restrict__ beta,
                         float* __restrict__ zout, float* __restrict__ xacc,
                         __half* __restrict__ zh, __half* __restrict__ xh){
  const int t = blockIdx.x;
  const int tid = threadIdx.x;
  float v0 = bias[tid];
  float v1 = bias[256+tid];
  for (int p=0; p<nparts; p++){
    v0 += zin[(size_t)p*T_*D_ + t*D_ + tid];
    v1 += zin[(size_t)p*T_*D_ + t*D_ + 256 + tid];
  }
  float s = v0+v1;
  float ss = v0*v0 + v1*v1;
  reduce2(s, ss);
  float m = s * (1.f/512.f);
  float var = ss * (1.f/512.f) - m*m;
  float rinv = rsqrtf(var + 1e-5f);
  float y0 = (v0 - m)*rinv*gamma[tid]     + beta[tid];
  float y1 = (v1 - m)*rinv*gamma[256+tid] + beta[256+tid];
  y0 = (y0 > 0.f) ? y0 : 0.01f*y0;
  y1 = (y1 > 0.f) ? y1 : 0.01f*y1;
  if (zout){
    zout[t*D_ + tid]       = y0;
    zout[t*D_ + 256 + tid] = y1;
  }
  if (xacc){
    float x0 = xacc[t*D_ + tid]       + y0;
    float x1 = xacc[t*D_ + 256 + tid] + y1;
    xacc[t*D_ + tid]       = x0;
    xacc[t*D_ + 256 + tid] = x1;
    if (xh){
      xh[t*D_ + tid]       = __float2half_rn(x0);
      xh[t*D_ + 256 + tid] = __float2half_rn(x1);
    }
  }
  if (zh){
    zh[t*D_ + tid]       = __float2half_rn(y0);
    zh[t*D_ + 256 + tid] = __float2half_rn(y1);
  }
}

// ================= launcher =================
extern "C" void kernel_launch(void* const* d_in, const int* in_sizes, int n_in,
                              void* d_out, int out_size) {
  const float*    x     = (const float*)d_in[0];
  const float*    state = (const float*)d_in[1];
  const unsigned* start = (const unsigned*)d_in[2];
  const float*    Wtr   = (const float*)d_in[3];
  const float*    Wc    = (const float*)d_in[4];
  const float*    a     = (const float*)d_in[5];
  const float*    b     = (const float*)d_in[6];
  const float*    W0    = (const float*)d_in[7];
  const float*    b0    = (const float*)d_in[8];
  const float*    g0    = (const float*)d_in[9];
  const float*    beta0 = (const float*)d_in[10];
  const float*    W1    = (const float*)d_in[11];
  const float*    b1    = (const float*)d_in[12];
  const float*    g1    = (const float*)d_in[13];
  const float*    beta1 = (const float*)d_in[14];
  float* out = (float*)d_out;

  float *px, *php, *pzt;
  __half *psh, *pw0h, *pw1h, *pwph, *pz0h, *pxh;
  cudaGetSymbolAddress((void**)&px,    g_x);
  cudaGetSymbolAddress((void**)&php,   g_hp);
  cudaGetSymbolAddress((void**)&pzt,   g_ztmp);
  cudaGetSymbolAddress((void**)&psh,   g_sclh);
  cudaGetSymbolAddress((void**)&pw0h,  g_w0h);
  cudaGetSymbolAddress((void**)&pw1h,  g_w1h);
  cudaGetSymbolAddress((void**)&pwph,  g_wph);
  cudaGetSymbolAddress((void**)&pz0h,  g_z0h);
  cudaGetSymbolAddress((void**)&pxh,   g_xh);

  cudaFuncSetAttribute(gemm1,   cudaFuncAttributeMaxDynamicSharedMemorySize, GEMM1_SMEM);
  cudaFuncSetAttribute(proj_uv, cudaFuncAttributeMaxDynamicSharedMemorySize, PROJ_SMEM);

  prep_all<<<(NPREP + 255)/256, 256>>>(W0, W1, Wtr, Wc, x, a, b);

  for (int l=0; l<L_; l++){
    proj_uv<<<dim3(1, T_/64), 256, PROJ_SMEM>>>(pxh, pwph + (size_t)l*128*D_);

    scan_passA<<<dim3(NCHUNK_, TR_), CC_>>>(start, l);
    scan_passC<<<dim3(NCHUNK_, TR_), CC_>>>(start, state, l);

    // h = scaled @ W0^T  (M=4096, N=512, K=8192), split-K=4
    gemm1<<<dim3(D_/128, T_/128, NSPLIT0_), 256, GEMM1_SMEM>>>(
        psh, pw0h + (size_t)l*D_*F_, php, F_, F_/NSPLIT0_, D_);
    ln_leaky<<<T_, 256>>>(php, NSPLIT0_, b0 + l*D_, g0 + l*D_, beta0 + l*D_,
                          nullptr, nullptr, pz0h, nullptr);

    // h = z0 @ W1^T  (M=4096, N=512, K=512), split-K=2
    gemm1<<<dim3(D_/128, T_/128, NSPLIT1_), 256, GEMM1_SMEM>>>(
        pz0h, pw1h + (size_t)l*D_*D_, php, D_, D_/NSPLIT1_, D_);
    float* zo = (l == L_-1) ? out : pzt;
    bool last = (l == L_-1);
    ln_leaky<<<T_, 256>>>(php, NSPLIT1_, b1 + l*D_, g1 + l*D_, beta1 + l*D_,
                          zo, px, nullptr, last ? nullptr : pxh);
  }
}

// round 14
// speedup vs baseline: 1.4313x; 1.0024x over previous
#include <cuda_runtime.h>
#include <cuda_fp16.h>
#include <math.h>
#include <stdint.h>

#define T_ 4096
#define D_ 512
#define TR_ 64
#define CC_ 64
#define L_ 3
#define F_ 8192
#define NCH_ 4096
#define NCHUNK_ 64
#define CHUNK_ 64
#define NSPLIT0_ 4
#define NSPLIT1_ 2

// ---------------- scratch ----------------
__device__ float g_x[T_*D_];
__device__ float g_u[T_*TR_];
__device__ float g_v[T_*CC_];
__device__ float2 g_Bend[NCHUNK_*NCH_];
__device__ float2 g_Amat[NCHUNK_*NCH_];
__device__ float2 g_dec[L_*NCH_];
__device__ float2 g_decL[L_*NCH_];
__device__ float g_hp[NSPLIT0_][T_*D_];
__device__ float g_ztmp[T_*D_];
__device__ __half g_sclh[(size_t)T_*F_];
__device__ __half g_w0h[L_*D_*F_];
__device__ __half g_w1h[L_*D_*D_];
__device__ __half g_wph[L_*128*D_];
__device__ __half g_z0h[T_*D_];
__device__ __half g_xh[T_*D_];

// ---------------- low-level helpers (baseline PTX @ compute_103) ----------------
__device__ __forceinline__ uint32_t sptr(const void* p){
  return (uint32_t)__cvta_generic_to_shared(p);
}
__device__ __forceinline__ void cp16(uint32_t s, const void* g){
  asm volatile("cp.async.cg.shared.global [%0], [%1], 16;" :: "r"(s), "l"(g));
}
#define CP_COMMIT() asm volatile("cp.async.commit_group;" ::: "memory")
#define CP_WAIT(n)  asm volatile("cp.async.wait_group %0;" :: "n"(n) : "memory")

__device__ __forceinline__ void ldsm4(uint32_t* r, uint32_t a){
  asm volatile("ldmatrix.sync.aligned.m8n8.x4.shared.b16 {%0,%1,%2,%3}, [%4];"
    : "=r"(r[0]),"=r"(r[1]),"=r"(r[2]),"=r"(r[3]) : "r"(a));
}
__device__ __forceinline__ void mma_h(float* d, const uint32_t* a, const uint32_t* b){
  asm volatile("mma.sync.aligned.m16n8k16.row.col.f32.f16.f16.f32 "
    "{%0,%1,%2,%3}, {%4,%5,%6,%7}, {%8,%9}, {%0,%1,%2,%3};"
    : "+f"(d[0]),"+f"(d[1]),"+f"(d[2]),"+f"(d[3])
    : "r"(a[0]),"r"(a[1]),"r"(a[2]),"r"(a[3]), "r"(b[0]),"r"(b[1]));
}

// ---------------- merged prep kernel ----------------
#define NW0 (L_*D_*F_)
#define NW1 (L_*D_*D_)
#define NWP (L_*128*D_)
#define NX  (T_*D_)
#define NDEC (L_*NCH_)
#define NPREP (NW0+NW1+NWP+NX+NDEC)

__global__ void prep_all(const float* __restrict__ W0, const float* __restrict__ W1,
                         const float* __restrict__ Wtr, const float* __restrict__ Wc,
                         const float* __restrict__ x,
                         const float* __restrict__ a, const float* __restrict__ b){
  int i = blockIdx.x*blockDim.x + threadIdx.x;
  if (i < NW0){
    g_w0h[i] = __float2half_rn(W0[i]);
  } else if (i < NW0+NW1){
    int k = i - NW0;
    g_w1h[k] = __float2half_rn(W1[k]);
  } else if (i < NW0+NW1+NWP){
    int idx = i - NW0 - NW1;
    int l = idx / (128*D_);
    int rem = idx % (128*D_);
    int row = rem / D_, k = rem % D_;
    float v = (row < 64) ? Wtr[((size_t)l*64+row)*D_+k] : Wc[((size_t)l*64+row-64)*D_+k];
    g_wph[idx] = __float2half_rn(v);
  } else if (i < NW0+NW1+NWP+NX){
    int k = i - NW0 - NW1 - NWP;
    float v = x[k];
    g_x[k] = v;
    g_xh[k] = __float2half_rn(v);
  } else if (i < NPREP){
    int k = i - NW0 - NW1 - NWP - NX;
    int l = k / NCH_;
    int ch = k % NCH_;
    int i0 = ch / CC_, j0 = ch % CC_;
    double ai = fabs((double)a[l*TR_+i0]);
    double bj = (double)b[l*CC_+j0];
    double rho = exp(-ai);
    double sb, cb; sincos(bj, &sb, &cb);
    g_dec[k] = make_float2((float)(rho*cb), (float)(rho*sb));
    double rhoL = exp(-ai*(double)CHUNK_);
    double sL, cL; sincos(bj*(double)CHUNK_, &sL, &cL);
    g_decL[k] = make_float2((float)(rhoL*cL), (float)(rhoL*sL));
  }
}

// ================= 1-term fp16 GEMM with split-K (even) =================
#define PADH 72
#define TILEH (128*PADH)
#define STAGE1 (2*TILEH)
#define GEMM1_SMEM (3*STAGE1*2)        // 110592 B

__device__ __forceinline__ void stage_load1(
    __half* s, const __half* Ah, const __half* Bh,
    int bm, int bn, int K, int k0, int tid)
{
  const __half* src[2] = {Ah, Bh};
  #pragma unroll
  for (int t=0;t<2;t++){
    int rb = (t==0)? bm : bn;
    #pragma unroll
    for (int q=0;q<4;q++){
      int chunk = tid + q*256;
      int row = chunk>>3, cc = chunk&7;
      uint32_t so = sptr(s + t*TILEH + row*PADH + cc*8);
      cp16(so, src[t] + (size_t)(rb+row)*K + k0 + cc*8);
    }
  }
}

__global__ void __launch_bounds__(256, 2)
gemm1(const __half* __restrict__ Ah, const __half* __restrict__ Bh,
      float* __restrict__ Cbase, int K, int KS, int Nc)
{
  extern __shared__ __half smh[];
  const int tid = threadIdx.x;
  const int wid = tid>>5, lane = tid&31;
  const int bm = blockIdx.y*128, bn = blockIdx.x*128;
  const int kz = blockIdx.z;
  const int kbase = kz * KS;
  float* C = Cbase + (size_t)kz * T_ * D_;
  const int wm = (wid>>1)*32;
  const int wn = (wid&1)*64;
  const int KT = KS>>6;

  float acc[2][8][4];
  #pragma unroll
  for (int i=0;i<2;i++)
    #pragma unroll
    for (int j=0;j<8;j++)
      #pragma unroll
      for (int q=0;q<4;q++) acc[i][j][q]=0.f;

  stage_load1(smh, Ah, Bh, bm, bn, K, kbase, tid);
  CP_COMMIT();
  if (KT > 1){
    stage_load1(smh + STAGE1, Ah, Bh, bm, bn, K, kbase + 64, tid);
    CP_COMMIT();
  }

  const int arow = lane & 15;
  const int acol8 = (lane>>4)*8;
  const int brow = (lane&7) + ((lane>>4)<<3);
  const int bsel = ((lane>>3)&1)*8;

  int bufc = 0;
  for (int c=0; c<KT; c++){
    if (c+1 < KT) { CP_WAIT(1); } else { CP_WAIT(0); }
    __syncthreads();

    __half* s = smh + bufc*STAGE1;
    const uint32_t sAh = sptr(s);
    const uint32_t sBh = sAh + TILEH*2;

    #pragma unroll
    for (int ks=0; ks<4; ks++){
      uint32_t ah[2][4], bh[4][4];
      #pragma unroll
      for (int mi=0; mi<2; mi++){
        uint32_t off = (uint32_t)((wm + mi*16 + arow)*PADH + ks*16 + acol8)*2;
        ldsm4(ah[mi], sAh + off);
      }
      #pragma unroll
      for (int p=0; p<4; p++){
        uint32_t off = (uint32_t)((wn + p*16 + brow)*PADH + ks*16 + bsel)*2;
        ldsm4(bh[p], sBh + off);
      }
      #pragma unroll
      for (int mi=0; mi<2; mi++)
        #pragma unroll
        for (int p=0; p<4; p++)
          #pragma unroll
          for (int h=0; h<2; h++)
            mma_h(acc[mi][p*2+h], ah[mi], &bh[p][h*2]);
    }

    if (c+2 < KT){
      int buf2 = bufc + 2; if (buf2 >= 3) buf2 -= 3;
      stage_load1(smh + buf2*STAGE1, Ah, Bh, bm, bn, K, kbase + (c+2)*64, tid);
      CP_COMMIT();
    }
    bufc++; if (bufc == 3) bufc = 0;
  }

  #pragma unroll
  for (int mi=0; mi<2; mi++){
    const int r0 = bm + wm + mi*16 + (lane>>2);
    const int c0 = bn + wn + (lane&3)*2;
    #pragma unroll
    for (int ni=0; ni<8; ni++){
      *(float2*)(C + (size_t)r0*Nc + c0 + ni*8)     = make_float2(acc[mi][ni][0], acc[mi][ni][1]);
      *(float2*)(C + (size_t)(r0+8)*Nc + c0 + ni*8) = make_float2(acc[mi][ni][2], acc[mi][ni][3]);
    }
  }
}

// ================= fused projection + uv (1-term) =================
#define PPADH 72
#define PA_TILE (64*PPADH)
#define PB_TILE (128*PPADH)
#define PSTAGE (PA_TILE + PB_TILE)
#define PROJ_SMEM (2*PSTAGE*2)

__device__ __forceinline__ void stage_load_proj(
    __half* s, const __half* Ah, const __half* Bh,
    int bm, int K, int k0, int tid)
{
  #pragma unroll
  for (int q=0;q<2;q++){
    int chunk = tid + q*256;
    int row = chunk>>3, cc = chunk&7;
    uint32_t so = sptr(s + row*PPADH + cc*8);
    cp16(so, Ah + (size_t)(bm+row)*K + k0 + cc*8);
  }
  #pragma unroll
  for (int q=0;q<4;q++){
    int chunk = tid + q*256;
    int row = chunk>>3, cc = chunk&7;
    uint32_t so = sptr(s + PA_TILE + row*PPADH + cc*8);
    cp16(so, Bh + (size_t)row*K + k0 + cc*8);
  }
}

__global__ void __launch_bounds__(256)
proj_uv(const __half* __restrict__ Ah, const __half* __restrict__ Bh)
{
  extern __shared__ __half smh[];
  __shared__ float ssum[4][64];
  __shared__ float sscale[64];
  const int tid = threadIdx.x;
  const int wid = tid>>5, lane = tid&31;
  const int bm = blockIdx.y*64;
  const int wm = (wid&1)*32;
  const int wn = (wid>>1)*32;
  const int K = D_;
  const int KT = K>>6;

  float acc[2][4][4];
  #pragma unroll
  for (int i=0;i<2;i++)
    #pragma unroll
    for (int j=0;j<4;j++)
      #pragma unroll
      for (int q=0;q<4;q++) acc[i][j][q]=0.f;

  stage_load_proj(smh, Ah, Bh, bm, K, 0, tid);
  CP_COMMIT();

  const int arow = lane & 15;
  const int acol8 = (lane>>4)*8;
  const int brow = (lane&7) + ((lane>>4)<<3);
  const int bsel = ((lane>>3)&1)*8;

  for (int c=0; c<KT; c++){
    if (c+1 < KT){
      stage_load_proj(smh + ((c+1)&1)*PSTAGE, Ah, Bh, bm, K, (c+1)*64, tid);
      CP_COMMIT();
      CP_WAIT(1);
    } else {
      CP_WAIT(0);
    }
    __syncthreads();

    __half* s = smh + (c&1)*PSTAGE;
    const uint32_t sAh = sptr(s);
    const uint32_t sBh = sAh + PA_TILE*2;

    #pragma unroll
    for (int ks=0; ks<4; ks++){
      uint32_t ah[2][4], bh[2][4];
      #pragma unroll
      for (int mi=0; mi<2; mi++){
        uint32_t off = (uint32_t)((wm + mi*16 + arow)*PPADH + ks*16 + acol8)*2;
        ldsm4(ah[mi], sAh + off);
      }
      #pragma unroll
      for (int p=0; p<2; p++){
        uint32_t off = (uint32_t)((wn + p*16 + brow)*PPADH + ks*16 + bsel)*2;
        ldsm4(bh[p], sBh + off);
      }
      #pragma unroll
      for (int mi=0; mi<2; mi++)
        #pragma unroll
        for (int p=0; p<2; p++)
          #pragma unroll
          for (int h=0; h<2; h++)
            mma_h(acc[mi][p*2+h], ah[mi], &bh[p][h*2]);
    }
    __syncthreads();
  }

  const int colblk = wid>>1;
  #pragma unroll
  for (int mi=0; mi<2; mi++){
    #pragma unroll
    for (int qh=0; qh<2; qh++){
      float sv = 0.f;
      #pragma unroll
      for (int ni=0; ni<4; ni++)
        sv += fabsf(acc[mi][ni][qh*2]) + fabsf(acc[mi][ni][qh*2+1]);
      sv += __shfl_xor_sync(0xffffffffu, sv, 1);
      sv += __shfl_xor_sync(0xffffffffu, sv, 2);
      if ((lane&3)==0)
        ssum[colblk][wm + mi*16 + qh*8 + (lane>>2)] = sv;
    }
  }
  __syncthreads();
  if (tid < 64){
    float str = ssum[0][tid] + ssum[1][tid];
    float sct = ssum[2][tid] + ssum[3][tid];
    sscale[tid] = __fdividef(1.f, 1e-8f + str*sct);
  }
  __syncthreads();
  #pragma unroll
  for (int mi=0; mi<2; mi++){
    #pragma unroll
    for (int ni=0; ni<4; ni++){
      #pragma unroll
      for (int q=0; q<4; q++){
        int rloc = wm + mi*16 + (q>>1)*8 + (lane>>2);
        int t = bm + rloc;
        int col = wn + (lane&3)*2 + ni*8 + (q&1);
        float vabs = fabsf(acc[mi][ni][q]);
        if (col < 64) g_u[t*TR_ + col] = vabs;
        else          g_v[t*CC_ + col - 64] = vabs * sscale[rloc];
      }
    }
  }
}

// ---------------- scan ----------------
// passA: SMEM-staged u + start (measured win in R13)
__global__ void scan_passA(const unsigned* __restrict__ start, int layer){
  const int i = blockIdx.y;
  const int c = blockIdx.x;
  const int j = threadIdx.x;
  const int ch = i*CC_+j;
  const int t0 = c*CHUNK_;
  __shared__ float su[CHUNK_];
  __shared__ unsigned sst[CHUNK_];
  su[j]  = g_u[(t0+j)*TR_ + i];
  sst[j] = start[t0+j];
  __syncthreads();
  float2 d = g_dec[layer*NCH_ + ch];
  const float dre = d.x, dim = d.y;
  float sre=0.f, sim=0.f;
  int reset = 0;
  #pragma unroll 4
  for (int tt=0; tt<CHUNK_; tt++){
    if (sst[tt]){ sre=0.f; sim=0.f; reset=1; }
    float p = su[tt]*g_v[(t0+tt)*CC_+j];
    float nre = fmaf(sre,dre, fmaf(-sim,dim,p));
    float nim = fmaf(sre,dim, sim*dre);
    sre=nre; sim=nim;
  }
  g_Bend[c*NCH_+ch]=make_float2(sre,sim);
  float2 A = make_float2(0.f, 0.f);
  if (!reset) A = g_decL[layer*NCH_ + ch];
  g_Amat[c*NCH_+ch]=A;
}

// passC: direct loads (R11 form — measured faster than staged)
__global__ void scan_passC(const unsigned* __restrict__ start,
                           const float* __restrict__ state, int layer){
  const int i = blockIdx.y, c = blockIdx.x, j = threadIdx.x;
  const int ch = i*CC_+j;
  float2 d = g_dec[layer*NCH_ + ch];
  const float dre = d.x, dim = d.y;
  float sre = state[layer*NCH_ + ch];
  float sim = 0.f;
  for (int cc=0; cc<c; cc++){
    float2 A = g_Amat[cc*NCH_+ch];
    float2 B = g_Bend[cc*NCH_+ch];
    float nr = A.x*sre - A.y*sim + B.x;
    float ni = A.x*sim + A.y*sre + B.y;
    sre=nr; sim=ni;
  }
  const int t0=c*CHUNK_;
  #pragma unroll 4
  for (int t=t0;t<t0+CHUNK_;t++){
    if (start[t]){ sre=0.f; sim=0.f; }
    float p = g_u[t*TR_+i]*g_v[t*CC_+j];
    float nre = fmaf(sre,dre, fmaf(-sim,dim,p));
    float nim = fmaf(sre,dim, sim*dre);
    sre=nre; sim=nim;
    float r2 = fmaf(sre,sre, sim*sim);
    float f;
    if (r2 > 1e-24f){
      float rr = sqrtf(r2);
      f = __fdividef(log1pf(rr), rr);
    } else {
      f = 1.f;
    }
    size_t o0 = (size_t)t*F_ + ch;
    g_sclh[o0]        = __float2half_rn(f*sim);
    g_sclh[o0 + NCH_] = __float2half_rn(f*sre);
  }
}

// ================= LayerNorm + leaky ReLU =================
__device__ __forceinline__ void reduce2(float &s, float &ss){
  __shared__ float sh[8], sh2[8];
  int lane = threadIdx.x & 31, w = threadIdx.x >> 5;
  #pragma unroll
  for (int o=16;o>0;o>>=1){
    s  += __shfl_down_sync(0xffffffffu, s,  o);
    ss += __shfl_down_sync(0xffffffffu, ss, o);
  }
  if (lane==0){ sh[w]=s; sh2[w]=ss; }
  __syncthreads();
  if (w==0){
    s  = (lane<8)? sh[lane]  : 0.f;
    ss = (lane<8)? sh2[lane] : 0.f;
    #pragma unroll
    for (int o=4;o>0;o>>=1){
      s  += __shfl_down_sync(0xffffffffu, s,  o);
      ss += __shfl_down_sync(0xffffffffu, ss, o);
    }
    if (lane==0){ sh[0]=s; sh2[0]=ss; }
  }
  __syncthreads();
  s = sh[0]; ss = sh2[0];
}

__global__ void ln_leaky(const float* __restrict__ zin, int nparts,
                         const float* __restrict__ bias,
                         const float* __restrict__ gamma, const float* __restrict__ beta,
                         float* __restrict__ zout, float* __restrict__ xacc,
                         __half* __restrict__ zh, __half* __restrict__ xh){
  const int t = blockIdx.x;
  const int tid = threadIdx.x;
  float v0 = bias[tid];
  float v1 = bias[256+tid];
  for (int p=0; p<nparts; p++){
    v0 += zin[(size_t)p*T_*D_ + t*D_ + tid];
    v1 += zin[(size_t)p*T_*D_ + t*D_ + 256 + tid];
  }
  float s = v0+v1;
  float ss = v0*v0 + v1*v1;
  reduce2(s, ss);
  float m = s * (1.f/512.f);
  float var = ss * (1.f/512.f) - m*m;
  float rinv = rsqrtf(var + 1e-5f);
  float y0 = (v0 - m)*rinv*gamma[tid]     + beta[tid];
  float y1 = (v1 - m)*rinv*gamma[256+tid] + beta[256+tid];
  y0 = (y0 > 0.f) ? y0 : 0.01f*y0;
  y1 = (y1 > 0.f) ? y1 : 0.01f*y1;
  if (zout){
    zout[t*D_ + tid]       = y0;
    zout[t*D_ + 256 + tid] = y1;
  }
  if (xacc){
    float x0 = xacc[t*D_ + tid]       + y0;
    float x1 = xacc[t*D_ + 256 + tid] + y1;
    xacc[t*D_ + tid]       = x0;
    xacc[t*D_ + 256 + tid] = x1;
    if (xh){
      xh[t*D_ + tid]       = __float2half_rn(x0);
      xh[t*D_ + 256 + tid] = __float2half_rn(x1);
    }
  }
  if (zh){
    zh[t*D_ + tid]       = __float2half_rn(y0);
    zh[t*D_ + 256 + tid] = __float2half_rn(y1);
  }
}

// ================= launcher =================
extern "C" void kernel_launch(void* const* d_in, const int* in_sizes, int n_in,
                              void* d_out, int out_size) {
  const float*    x     = (const float*)d_in[0];
  const float*    state = (const float*)d_in[1];
  const unsigned* start = (const unsigned*)d_in[2];
  const float*    Wtr   = (const float*)d_in[3];
  const float*    Wc    = (const float*)d_in[4];
  const float*    a     = (const float*)d_in[5];
  const float*    b     = (const float*)d_in[6];
  const float*    W0    = (const float*)d_in[7];
  const float*    b0    = (const float*)d_in[8];
  const float*    g0    = (const float*)d_in[9];
  const float*    beta0 = (const float*)d_in[10];
  const float*    W1    = (const float*)d_in[11];
  const float*    b1    = (const float*)d_in[12];
  const float*    g1    = (const float*)d_in[13];
  const float*    beta1 = (const float*)d_in[14];
  float* out = (float*)d_out;

  float *px, *php, *pzt;
  __half *psh, *pw0h, *pw1h, *pwph, *pz0h, *pxh;
  cudaGetSymbolAddress((void**)&px,    g_x);
  cudaGetSymbolAddress((void**)&php,   g_hp);
  cudaGetSymbolAddress((void**)&pzt,   g_ztmp);
  cudaGetSymbolAddress((void**)&psh,   g_sclh);
  cudaGetSymbolAddress((void**)&pw0h,  g_w0h);
  cudaGetSymbolAddress((void**)&pw1h,  g_w1h);
  cudaGetSymbolAddress((void**)&pwph,  g_wph);
  cudaGetSymbolAddress((void**)&pz0h,  g_z0h);
  cudaGetSymbolAddress((void**)&pxh,   g_xh);

  cudaFuncSetAttribute(gemm1,   cudaFuncAttributeMaxDynamicSharedMemorySize, GEMM1_SMEM);
  cudaFuncSetAttribute(proj_uv, cudaFuncAttributeMaxDynamicSharedMemorySize, PROJ_SMEM);

  prep_all<<<(NPREP + 255)/256, 256>>>(W0, W1, Wtr, Wc, x, a, b);

  for (int l=0; l<L_; l++){
    proj_uv<<<dim3(1, T_/64), 256, PROJ_SMEM>>>(pxh, pwph + (size_t)l*128*D_);

    scan_passA<<<dim3(NCHUNK_, TR_), CC_>>>(start, l);
    scan_passC<<<dim3(NCHUNK_, TR_), CC_>>>(start, state, l);

    // h = scaled @ W0^T  (M=4096, N=512, K=8192), split-K=4
    gemm1<<<dim3(D_/128, T_/128, NSPLIT0_), 256, GEMM1_SMEM>>>(
        psh, pw0h + (size_t)l*D_*F_, php, F_, F_/NSPLIT0_, D_);
    ln_leaky<<<T_, 256>>>(php, NSPLIT0_, b0 + l*D_, g0 + l*D_, beta0 + l*D_,
                          nullptr, nullptr, pz0h, nullptr);

    // h = z0 @ W1^T  (M=4096, N=512, K=512), split-K=2
    gemm1<<<dim3(D_/128, T_/128, NSPLIT1_), 256, GEMM1_SMEM>>>(
        pz0h, pw1h + (size_t)l*D_*D_, php, D_, D_/NSPLIT1_, D_);
    float* zo = (l == L_-1) ? out : pzt;
    bool last = (l == L_-1);
    ln_leaky<<<T_, 256>>>(php, NSPLIT1_, b1 + l*D_, g1 + l*D_, beta1 + l*D_,
                          zo, px, nullptr, last ? nullptr : pxh);
  }
}